// round 15
// baseline (speedup 1.0000x reference)
#include <cuda_runtime.h>
#include <cuda_fp16.h>
#include <cstdint>

#define DMODEL 1024
#define NHEAD 16
#define DKH 64
#define BATCH 4
#define SEQ 2048
#define MTOT (BATCH*SEQ)   // 8192
#define QKVD (3*DMODEL)    // 3072
#define STR 72             // smem row stride in halves (144B = 9*16B)
#define LOG2E 1.4426950408889634f

// ---------------- scratch (static device globals; no allocation) ----------
__device__ __align__(16) __half g_XH[MTOT*DMODEL];
__device__ __align__(16) __half g_QKVH[MTOT*QKVD];
__device__ __align__(16) __half g_AOH[MTOT*DMODEL];
__device__ __align__(16) __half g_WTH[4*DMODEL*DMODEL];  // transposed [N,K] fp16
__device__ float g_MF[BATCH*SEQ];                        // additive mask (log2 domain)

// ---------------- helpers ---------------------------------------------------
__device__ __forceinline__ uint32_t smem_u32(const void* p) {
    uint32_t a;
    asm("{ .reg .u64 t; cvta.to.shared.u64 t, %1; cvt.u32.u64 %0, t; }"
        : "=r"(a) : "l"(p));
    return a;
}
__device__ __forceinline__ void cp16(uint32_t smem_addr, const void* gptr) {
    asm volatile("cp.async.cg.shared.global [%0], [%1], 16;"
                 :: "r"(smem_addr), "l"(gptr));
}
#define CP_COMMIT() asm volatile("cp.async.commit_group;" ::: "memory")

__device__ __forceinline__ void ldmx4(uint32_t* r, uint32_t addr) {
    asm volatile("ldmatrix.sync.aligned.m8n8.x4.shared.b16 {%0,%1,%2,%3}, [%4];"
        : "=r"(r[0]), "=r"(r[1]), "=r"(r[2]), "=r"(r[3]) : "r"(addr));
}
__device__ __forceinline__ void ldmx4t(uint32_t* r, uint32_t addr) {
    asm volatile("ldmatrix.sync.aligned.m8n8.x4.trans.shared.b16 {%0,%1,%2,%3}, [%4];"
        : "=r"(r[0]), "=r"(r[1]), "=r"(r[2]), "=r"(r[3]) : "r"(addr));
}
__device__ __forceinline__ void mma_f16(float* c, const uint32_t* a,
                                        const uint32_t* b) {
    asm volatile(
        "mma.sync.aligned.m16n8k16.row.col.f32.f16.f16.f32 "
        "{%0,%1,%2,%3}, {%4,%5,%6,%7}, {%8,%9}, {%0,%1,%2,%3};"
        : "+f"(c[0]), "+f"(c[1]), "+f"(c[2]), "+f"(c[3])
        : "r"(a[0]), "r"(a[1]), "r"(a[2]), "r"(a[3]), "r"(b[0]), "r"(b[1]));
}
__device__ __forceinline__ uint32_t packh2(float a, float b) {
    __half2 h = __floats2half2_rn(a, b);
    return *(uint32_t*)&h;
}
__device__ __forceinline__ uint32_t h2exp2(uint32_t x) {
    uint32_t r;
    asm("ex2.approx.f16x2 %0, %1;" : "=r"(r) : "r"(x));
    return r;
}

// ---------------- mask prep (log2 domain) -----------------------------------
__global__ void maskprep_kernel(const int* __restrict__ m, float* __restrict__ mf) {
    int i = blockIdx.x * 256 + threadIdx.x;
    if (i < BATCH * SEQ) mf[i] = (1.0f - (float)m[i]) * (-1e9f * LOG2E);
}

// ---------------- X fp32 -> fp16 -------------------------------------------
__global__ __launch_bounds__(256) void xtohalf_kernel(
        const float* __restrict__ in, __half* __restrict__ out)
{
    int i = blockIdx.x * 256 + threadIdx.x;
    float4 v = ((const float4*)in)[i];
    ((__half2*)out)[2*i]   = __floats2half2_rn(v.x, v.y);
    ((__half2*)out)[2*i+1] = __floats2half2_rn(v.z, v.w);
}

// ---------------- fused transpose [K,N]->[N,K] + fp16 ----------------------
__global__ __launch_bounds__(256) void transpose_kernel(
        const float* __restrict__ Wq, const float* __restrict__ Wk,
        const float* __restrict__ Wv, const float* __restrict__ Wo,
        __half* __restrict__ wt)
{
    __shared__ float t[32][33];
    int z = blockIdx.z;
    const float* in = (z == 0) ? Wq : (z == 1) ? Wk : (z == 2) ? Wv : Wo;
    __half* out = wt + (size_t)z * DMODEL * DMODEL;
    int x = blockIdx.x * 32 + threadIdx.x;
    int y = blockIdx.y * 32 + threadIdx.y;
    #pragma unroll
    for (int j = 0; j < 32; j += 8)
        t[threadIdx.y + j][threadIdx.x] = in[(size_t)(y + j) * DMODEL + x];
    __syncthreads();
    x = blockIdx.y * 32 + threadIdx.x;
    y = blockIdx.x * 32 + threadIdx.y;
    #pragma unroll
    for (int j = 0; j < 32; j += 8)
        out[(size_t)(y + j) * DMODEL + x] =
            __float2half_rn(t[threadIdx.x][threadIdx.y + j]);
}

// ---------------- fp16 mma GEMM: C[M,N] = A[M,K] @ Bt[N,K]^T ----------------
// CTA 128x128, k-tile 64 halves, 3-stage cp.async, 2 CTA/SM. (round-11 exact)
#define NKT2 (DMODEL/64)
#define STAGE_BYTES (2*128*STR*2)
#define TGEMM_SMEM (3*STAGE_BYTES)

template<int HOUT>
__global__ __launch_bounds__(256, 2) void tgemm_h_kernel(
        const __half* __restrict__ A, const __half* __restrict__ Bt,
        void* __restrict__ Cv, int N, int qcols, float qscale)
{
    extern __shared__ char smb[];
    const int tid  = threadIdx.x;
    const int lane = tid & 31;
    const int wid  = tid >> 5;
    const int bm = blockIdx.y * 128;
    const int bn = blockIdx.x * 128;
    const int wm = (wid & 1) * 64;
    const int wn = (wid >> 1) * 32;
    const int K = DMODEL;

    float acc[4][4][4];
    #pragma unroll
    for (int mt = 0; mt < 4; mt++)
        #pragma unroll
        for (int nt = 0; nt < 4; nt++)
            #pragma unroll
            for (int i = 0; i < 4; i++) acc[mt][nt][i] = 0.0f;

    const __half* gA = A  + (size_t)bm * K;
    const __half* gB = Bt + (size_t)bn * K;

    auto load_stage = [&](int s, int kt) {
        uint32_t base  = smem_u32(smb) + s * STAGE_BYTES;
        uint32_t baseB = base + 128 * STR * 2;
        const __half* pa = gA + kt * 64;
        const __half* pb = gB + kt * 64;
        #pragma unroll
        for (int i = 0; i < 4; i++) {
            int idx = tid + i * 256;
            int r = idx >> 3;
            int c = idx & 7;
            uint32_t off = (uint32_t)(r * STR * 2 + c * 16);
            cp16(base  + off, pa + (size_t)r * K + c * 8);
            cp16(baseB + off, pb + (size_t)r * K + c * 8);
        }
        CP_COMMIT();
    };

    load_stage(0, 0);
    load_stage(1, 1);

    const int lr = lane >> 2;
    const int lc = lane & 3;
    const int a_row = (lane & 7) + ((lane >> 3) & 1) * 8;
    const int a_k   = (lane >> 4) * 8;
    const int b_row = (lane & 7) + (lane >> 4) * 8;
    const int b_k   = ((lane >> 3) & 1) * 8;

    #pragma unroll 3
    for (int kt = 0; kt < NKT2; kt++) {
        int s = kt % 3;
        if (kt < NKT2 - 1) asm volatile("cp.async.wait_group 1;" ::: "memory");
        else               asm volatile("cp.async.wait_group 0;" ::: "memory");
        __syncthreads();

        const __half* As = (const __half*)(smb + s * STAGE_BYTES);
        const __half* Bs = As + 128 * STR;

        #pragma unroll
        for (int ks = 0; ks < 4; ks++) {
            int k0 = ks * 16;
            uint32_t a[4][4], b[2][4];
            #pragma unroll
            for (int mt = 0; mt < 4; mt++)
                ldmx4(a[mt], smem_u32(As + (wm + mt * 16 + a_row) * STR + k0 + a_k));
            #pragma unroll
            for (int ntp = 0; ntp < 2; ntp++)
                ldmx4(b[ntp], smem_u32(Bs + (wn + ntp * 16 + b_row) * STR + k0 + b_k));
            #pragma unroll
            for (int mt = 0; mt < 4; mt++) {
                mma_f16(acc[mt][0], a[mt], &b[0][0]);
                mma_f16(acc[mt][1], a[mt], &b[0][2]);
                mma_f16(acc[mt][2], a[mt], &b[1][0]);
                mma_f16(acc[mt][3], a[mt], &b[1][2]);
            }
        }
        if (kt + 2 < NKT2) load_stage((kt + 2) % 3, kt + 2);
    }

    const float sc = (bn < qcols) ? qscale : 1.0f;
    #pragma unroll
    for (int mt = 0; mt < 4; mt++) {
        int row = bm + wm + mt * 16 + lr;
        #pragma unroll
        for (int nt = 0; nt < 4; nt++) {
            int col = bn + wn + nt * 8 + 2 * lc;
            float c0 = acc[mt][nt][0] * sc, c1 = acc[mt][nt][1] * sc;
            float c2 = acc[mt][nt][2] * sc, c3 = acc[mt][nt][3] * sc;
            if (HOUT) {
                __half* C = (__half*)Cv;
                *(__half2*)(C + (size_t)row * N + col) = __floats2half2_rn(c0, c1);
                *(__half2*)(C + (size_t)(row + 8) * N + col) = __floats2half2_rn(c2, c3);
            } else {
                float* C = (float*)Cv;
                *(float2*)(C + (size_t)row * N + col) = make_float2(c0, c1);
                *(float2*)(C + (size_t)(row + 8) * N + col) = make_float2(c2, c3);
            }
        }
    }
}

// ---------------- fp16 mma flash attention (online softmax) -----------------
// 512 thr / 16 warps; 256 queries x 64 keys per iter; 4-stage K/V; 1 CTA/SM.
// Per-warp state identical to the 128-q config; K/V L2 traffic halved.
#define QTILE 256
#define ATHREADS 512
#define NTK (SEQ/64)
#define NSTG 4
#define AQ_HALVES (QTILE*STR)
#define AK_HALVES (64*STR)
#define ATTN_SMEM ((AQ_HALVES + NSTG*2*AK_HALVES)*2 + NSTG*64*(int)sizeof(float))

__global__ __launch_bounds__(ATHREADS, 1) void attn_mma_kernel(
        const __half* __restrict__ QKV, const float* __restrict__ MF,
        __half* __restrict__ O)
{
    extern __shared__ char smb[];
    __half* Qs  = (__half*)smb;
    __half* Kss = Qs + AQ_HALVES;
    __half* Vss = Kss + NSTG * AK_HALVES;
    float*  Mks = (float*)(Vss + NSTG * AK_HALVES);

    const int tid  = threadIdx.x;
    const int wid  = tid >> 5;         // 0..15
    const int lane = tid & 31;
    const int lr = lane >> 2;
    const int lc = lane & 3;
    const int wq = wid * 16;           // warp's query-row offset (0..240)
    const int qt = blockIdx.x;
    const int h  = blockIdx.y;
    const int b  = blockIdx.z;

    const int a_row = (lane & 7) + ((lane >> 3) & 1) * 8;
    const int a_k   = (lane >> 4) * 8;
    const int b_row = (lane & 7) + (lane >> 4) * 8;
    const int b_k   = ((lane >> 3) & 1) * 8;

    const size_t qrow0 = (size_t)b * SEQ + (size_t)qt * QTILE;
    const __half* Qg = QKV + qrow0 * QKVD + h * DKH;
    const __half* Kb = QKV + (size_t)b * SEQ * QKVD + DMODEL + h * DKH;
    const __half* Vb = QKV + (size_t)b * SEQ * QKVD + 2 * DMODEL + h * DKH;
    const float* Mb = MF + (size_t)b * SEQ;

    // Q tile 256x64 (pre-scaled by 0.125*log2e in GEMM epilogue), group 0
    {
        uint32_t qbase = smem_u32(Qs);
        #pragma unroll
        for (int t = 0; t < 4; t++) {
            int idx = tid + t * ATHREADS;   // 0..2047
            int r = idx >> 3;               // 0..255
            int c = idx & 7;
            cp16(qbase + (uint32_t)(r * STR * 2 + c * 16),
                 Qg + (size_t)r * QKVD + c * 8);
        }
    }

    auto load_stage = [&](int s, int kt) {
        const __half* Kg = Kb + (size_t)kt * 64 * QKVD;
        const __half* Vg = Vb + (size_t)kt * 64 * QKVD;
        uint32_t kbase = smem_u32(Kss + s * AK_HALVES);
        uint32_t vbase = smem_u32(Vss + s * AK_HALVES);
        // 64 rows x 8 chunks = 512 slots = exactly 1 per thread
        int r = tid >> 3;
        int c = tid & 7;
        uint32_t off = (uint32_t)(r * STR * 2 + c * 16);
        cp16(kbase + off, Kg + (size_t)r * QKVD + c * 8);
        cp16(vbase + off, Vg + (size_t)r * QKVD + c * 8);
        if (tid < 16)
            cp16(smem_u32(Mks + s * 64) + tid * 16, Mb + kt * 64 + tid * 4);
        CP_COMMIT();
    };

    load_stage(0, 0);   // group 0 also carries the Q cp.asyncs
    load_stage(1, 1);
    load_stage(2, 2);

    // wait for Q (group 0) and hoist Q fragments into registers
    asm volatile("cp.async.wait_group 2;" ::: "memory");
    __syncthreads();
    uint32_t qf[4][4];
    #pragma unroll
    for (int ks = 0; ks < 4; ks++)
        ldmx4(qf[ks], smem_u32(Qs + (wq + a_row) * STR + ks * 16 + a_k));

    float o[8][4];
    #pragma unroll
    for (int nt = 0; nt < 8; nt++)
        #pragma unroll
        for (int i = 0; i < 4; i++) o[nt][i] = 0.0f;
    float mst0 = -1e30f, mst1 = -1e30f, lst0 = 0.0f, lst1 = 0.0f;

    const uint32_t ones2 = packh2(1.0f, 1.0f);
    const uint32_t bones[2] = { ones2, ones2 };

    #pragma unroll 4
    for (int kt = 0; kt < NTK; kt++) {
        int s = kt & 3;
        if (kt < NTK - 2)       asm volatile("cp.async.wait_group 2;" ::: "memory");
        else if (kt == NTK - 2) asm volatile("cp.async.wait_group 1;" ::: "memory");
        else                    asm volatile("cp.async.wait_group 0;" ::: "memory");
        __syncthreads();

        const __half* Kt = Kss + s * AK_HALVES;
        const __half* Vt = Vss + s * AK_HALVES;
        const float* mk = Mks + s * 64;

        // ---- scores: S = (Q*log2e/8) K^T ----
        float sa[8][4];
        #pragma unroll
        for (int nt = 0; nt < 8; nt++)
            #pragma unroll
            for (int i = 0; i < 4; i++) sa[nt][i] = 0.0f;

        #pragma unroll
        for (int ks = 0; ks < 4; ks++) {
            int k0 = ks * 16;
            #pragma unroll
            for (int ntp = 0; ntp < 4; ntp++) {
                uint32_t bb[4];
                ldmx4(bb, smem_u32(Kt + (ntp * 16 + b_row) * STR + k0 + b_k));
                mma_f16(sa[2 * ntp],     qf[ks], &bb[0]);
                mma_f16(sa[2 * ntp + 1], qf[ks], &bb[2]);
            }
        }

        // ---- online softmax (log2 domain) ----
        float rm0 = -1e30f, rm1 = -1e30f;
        #pragma unroll
        for (int nt = 0; nt < 8; nt++) {
            float2 m = *(const float2*)(mk + nt * 8 + 2 * lc);
            sa[nt][0] += m.x; sa[nt][1] += m.y;
            sa[nt][2] += m.x; sa[nt][3] += m.y;
            rm0 = fmaxf(rm0, fmaxf(sa[nt][0], sa[nt][1]));
            rm1 = fmaxf(rm1, fmaxf(sa[nt][2], sa[nt][3]));
        }
        rm0 = fmaxf(rm0, __shfl_xor_sync(0xffffffffu, rm0, 1));
        rm0 = fmaxf(rm0, __shfl_xor_sync(0xffffffffu, rm0, 2));
        rm1 = fmaxf(rm1, __shfl_xor_sync(0xffffffffu, rm1, 1));
        rm1 = fmaxf(rm1, __shfl_xor_sync(0xffffffffu, rm1, 2));

        float nm0 = fmaxf(mst0, rm0), nm1 = fmaxf(mst1, rm1);
        float al0 = exp2f(mst0 - nm0), al1 = exp2f(mst1 - nm1);
        mst0 = nm0; mst1 = nm1;

        // P = 2^(s-m) pairwise in fp16 (ex2.approx.f16x2)
        uint32_t ph[8][2];
        #pragma unroll
        for (int nt = 0; nt < 8; nt++) {
            ph[nt][0] = h2exp2(packh2(sa[nt][0] - nm0, sa[nt][1] - nm0));
            ph[nt][1] = h2exp2(packh2(sa[nt][2] - nm1, sa[nt][3] - nm1));
            o[nt][0] *= al0; o[nt][1] *= al0;
            o[nt][2] *= al1; o[nt][3] *= al1;
        }

        // ---- O += P V ; row-sum(P) via ones-B MMA ----
        float lacc[4] = {0.0f, 0.0f, 0.0f, 0.0f};
        #pragma unroll
        for (int ks = 0; ks < 4; ks++) {
            int k0 = ks * 16;
            uint32_t a[4] = { ph[2 * ks][0], ph[2 * ks][1],
                              ph[2 * ks + 1][0], ph[2 * ks + 1][1] };
            #pragma unroll
            for (int ntp = 0; ntp < 4; ntp++) {
                uint32_t bb[4];
                ldmx4t(bb, smem_u32(Vt + (k0 + a_row) * STR + ntp * 16 + a_k));
                mma_f16(o[2 * ntp],     a, &bb[0]);
                mma_f16(o[2 * ntp + 1], a, &bb[2]);
            }
            mma_f16(lacc, a, bones);
        }
        lst0 = lst0 * al0 + lacc[0];
        lst1 = lst1 * al1 + lacc[2];

        if (kt + 3 < NTK) load_stage((kt + 3) & 3, kt + 3);
    }

    float inv0 = 1.0f / lst0;
    float inv1 = 1.0f / lst1;
    __half* Og = O + qrow0 * DMODEL + h * DKH;
    #pragma unroll
    for (int nt = 0; nt < 8; nt++) {
        int col = nt * 8 + 2 * lc;
        *(__half2*)(Og + (size_t)(wq + lr) * DMODEL + col) =
            __floats2half2_rn(o[nt][0] * inv0, o[nt][1] * inv0);
        *(__half2*)(Og + (size_t)(wq + lr + 8) * DMODEL + col) =
            __floats2half2_rn(o[nt][2] * inv1, o[nt][3] * inv1);
    }
}

// ---------------- launch ---------------------------------------------------
extern "C" void kernel_launch(void* const* d_in, const int* in_sizes, int n_in,
                              void* d_out, int out_size) {
    const float* X    = (const float*)d_in[0];
    const int*   mask = (const int*)d_in[1];
    const float* Wq   = (const float*)d_in[2];
    const float* Wk   = (const float*)d_in[3];
    const float* Wv   = (const float*)d_in[4];
    const float* Wo   = (const float*)d_in[5];
    float* out = (float*)d_out;

    __half *xh, *qkvh, *aoh, *wth;
    float *mf;
    cudaGetSymbolAddress((void**)&xh,   g_XH);
    cudaGetSymbolAddress((void**)&qkvh, g_QKVH);
    cudaGetSymbolAddress((void**)&aoh,  g_AOH);
    cudaGetSymbolAddress((void**)&wth,  g_WTH);
    cudaGetSymbolAddress((void**)&mf,   g_MF);

    cudaFuncSetAttribute(attn_mma_kernel,
                         cudaFuncAttributeMaxDynamicSharedMemorySize, ATTN_SMEM);
    cudaFuncSetAttribute(tgemm_h_kernel<0>,
                         cudaFuncAttributeMaxDynamicSharedMemorySize, TGEMM_SMEM);
    cudaFuncSetAttribute(tgemm_h_kernel<1>,
                         cudaFuncAttributeMaxDynamicSharedMemorySize, TGEMM_SMEM);

    maskprep_kernel<<<(BATCH*SEQ + 255) / 256, 256>>>(mask, mf);
    xtohalf_kernel<<<MTOT * DMODEL / 4 / 256, 256>>>(X, xh);
    transpose_kernel<<<dim3(32, 32, 4), dim3(32, 8)>>>(Wq, Wk, Wv, Wo, wth);

    // fused Q|K|V projection; Q cols pre-scaled by 0.125*log2e
    tgemm_h_kernel<1><<<dim3(QKVD / 128, MTOT / 128), 256, TGEMM_SMEM>>>(
        xh, wth, qkvh, QKVD, DMODEL, 0.125f * LOG2E);

    attn_mma_kernel<<<dim3(SEQ / QTILE, NHEAD, BATCH), ATHREADS, ATTN_SMEM>>>(
        qkvh, mf, aoh);

    tgemm_h_kernel<0><<<dim3(DMODEL / 128, MTOT / 128), 256, TGEMM_SMEM>>>(
        aoh, wth + 3 * DMODEL * DMODEL, out, DMODEL, 0, 1.0f);
}

// round 16
// speedup vs baseline: 1.0880x; 1.0880x over previous
#include <cuda_runtime.h>
#include <cuda_fp16.h>
#include <cstdint>

#define DMODEL 1024
#define NHEAD 16
#define DKH 64
#define BATCH 4
#define SEQ 2048
#define MTOT (BATCH*SEQ)   // 8192
#define QKVD (3*DMODEL)    // 3072
#define STR 72             // smem row stride in halves (144B = 9*16B)
#define LOG2E 1.4426950408889634f

// ---------------- scratch (static device globals; no allocation) ----------
__device__ __align__(16) __half g_XH[MTOT*DMODEL];
__device__ __align__(16) __half g_QKVH[MTOT*QKVD];
__device__ __align__(16) __half g_AOH[MTOT*DMODEL];
__device__ __align__(16) __half g_WTH[4*DMODEL*DMODEL];  // transposed [N,K] fp16
__device__ float g_MF[BATCH*SEQ];                        // additive mask (log2 domain)

// ---------------- helpers ---------------------------------------------------
__device__ __forceinline__ uint32_t smem_u32(const void* p) {
    uint32_t a;
    asm("{ .reg .u64 t; cvta.to.shared.u64 t, %1; cvt.u32.u64 %0, t; }"
        : "=r"(a) : "l"(p));
    return a;
}
__device__ __forceinline__ void cp16(uint32_t smem_addr, const void* gptr) {
    asm volatile("cp.async.cg.shared.global [%0], [%1], 16;"
                 :: "r"(smem_addr), "l"(gptr));
}
#define CP_COMMIT() asm volatile("cp.async.commit_group;" ::: "memory")

__device__ __forceinline__ void ldmx4(uint32_t* r, uint32_t addr) {
    asm volatile("ldmatrix.sync.aligned.m8n8.x4.shared.b16 {%0,%1,%2,%3}, [%4];"
        : "=r"(r[0]), "=r"(r[1]), "=r"(r[2]), "=r"(r[3]) : "r"(addr));
}
__device__ __forceinline__ void ldmx4t(uint32_t* r, uint32_t addr) {
    asm volatile("ldmatrix.sync.aligned.m8n8.x4.trans.shared.b16 {%0,%1,%2,%3}, [%4];"
        : "=r"(r[0]), "=r"(r[1]), "=r"(r[2]), "=r"(r[3]) : "r"(addr));
}
__device__ __forceinline__ void mma_f16(float* c, const uint32_t* a,
                                        const uint32_t* b) {
    asm volatile(
        "mma.sync.aligned.m16n8k16.row.col.f32.f16.f16.f32 "
        "{%0,%1,%2,%3}, {%4,%5,%6,%7}, {%8,%9}, {%0,%1,%2,%3};"
        : "+f"(c[0]), "+f"(c[1]), "+f"(c[2]), "+f"(c[3])
        : "r"(a[0]), "r"(a[1]), "r"(a[2]), "r"(a[3]), "r"(b[0]), "r"(b[1]));
}
__device__ __forceinline__ uint32_t packh2(float a, float b) {
    __half2 h = __floats2half2_rn(a, b);
    return *(uint32_t*)&h;
}
__device__ __forceinline__ uint32_t h2exp2(uint32_t x) {
    uint32_t r;
    asm("ex2.approx.f16x2 %0, %1;" : "=r"(r) : "r"(x));
    return r;
}

// ---------------- fused prep: W transpose+fp16 / X fp16 / mask --------------
// grid (32, 32, 5): z=0..3 transpose W_z; z=4 grid-stride xtohalf + maskprep.
__global__ __launch_bounds__(256) void prep_kernel(
        const float* __restrict__ X, const int* __restrict__ mask,
        const float* __restrict__ Wq, const float* __restrict__ Wk,
        const float* __restrict__ Wv, const float* __restrict__ Wo,
        __half* __restrict__ xh, __half* __restrict__ wt,
        float* __restrict__ mf)
{
    const int z = blockIdx.z;
    if (z < 4) {
        __shared__ float t[32][33];
        const float* in = (z == 0) ? Wq : (z == 1) ? Wk : (z == 2) ? Wv : Wo;
        __half* out = wt + (size_t)z * DMODEL * DMODEL;
        const int tx = threadIdx.x & 31;
        const int ty = threadIdx.x >> 5;      // 0..7
        int x = blockIdx.x * 32 + tx;
        int y = blockIdx.y * 32 + ty;
        #pragma unroll
        for (int j = 0; j < 32; j += 8)
            t[ty + j][tx] = in[(size_t)(y + j) * DMODEL + x];
        __syncthreads();
        x = blockIdx.y * 32 + tx;
        y = blockIdx.x * 32 + ty;
        #pragma unroll
        for (int j = 0; j < 32; j += 8)
            out[(size_t)(y + j) * DMODEL + x] = __float2half_rn(t[tx][ty + j]);
    } else {
        const int bid = blockIdx.y * 32 + blockIdx.x;        // 0..1023
        // X -> fp16, 2M float4 over 1024 blocks x 256 threads (8 iters)
        #pragma unroll
        for (int it = 0; it < 8; it++) {
            int i = (it * 1024 + bid) * 256 + threadIdx.x;
            float4 v = ((const float4*)X)[i];
            ((__half2*)xh)[2*i]   = __floats2half2_rn(v.x, v.y);
            ((__half2*)xh)[2*i+1] = __floats2half2_rn(v.z, v.w);
        }
        if (bid < 32) {                                      // 32*256 = 8192
            int i = bid * 256 + threadIdx.x;
            mf[i] = (1.0f - (float)mask[i]) * (-1e9f * LOG2E);
        }
    }
}

// ---------------- fp16 mma GEMM: C[M,N] = A[M,K] @ Bt[N,K]^T ----------------
// CTA 128x128, k-tile 64 halves, 3-stage cp.async, 2 CTA/SM. (round-11 exact)
#define NKT2 (DMODEL/64)
#define STAGE_BYTES (2*128*STR*2)
#define TGEMM_SMEM (3*STAGE_BYTES)

template<int HOUT>
__global__ __launch_bounds__(256, 2) void tgemm_h_kernel(
        const __half* __restrict__ A, const __half* __restrict__ Bt,
        void* __restrict__ Cv, int N, int qcols, float qscale)
{
    extern __shared__ char smb[];
    const int tid  = threadIdx.x;
    const int lane = tid & 31;
    const int wid  = tid >> 5;
    const int bm = blockIdx.y * 128;
    const int bn = blockIdx.x * 128;
    const int wm = (wid & 1) * 64;
    const int wn = (wid >> 1) * 32;
    const int K = DMODEL;

    float acc[4][4][4];
    #pragma unroll
    for (int mt = 0; mt < 4; mt++)
        #pragma unroll
        for (int nt = 0; nt < 4; nt++)
            #pragma unroll
            for (int i = 0; i < 4; i++) acc[mt][nt][i] = 0.0f;

    const __half* gA = A  + (size_t)bm * K;
    const __half* gB = Bt + (size_t)bn * K;

    auto load_stage = [&](int s, int kt) {
        uint32_t base  = smem_u32(smb) + s * STAGE_BYTES;
        uint32_t baseB = base + 128 * STR * 2;
        const __half* pa = gA + kt * 64;
        const __half* pb = gB + kt * 64;
        #pragma unroll
        for (int i = 0; i < 4; i++) {
            int idx = tid + i * 256;
            int r = idx >> 3;
            int c = idx & 7;
            uint32_t off = (uint32_t)(r * STR * 2 + c * 16);
            cp16(base  + off, pa + (size_t)r * K + c * 8);
            cp16(baseB + off, pb + (size_t)r * K + c * 8);
        }
        CP_COMMIT();
    };

    load_stage(0, 0);
    load_stage(1, 1);

    const int lr = lane >> 2;
    const int lc = lane & 3;
    const int a_row = (lane & 7) + ((lane >> 3) & 1) * 8;
    const int a_k   = (lane >> 4) * 8;
    const int b_row = (lane & 7) + (lane >> 4) * 8;
    const int b_k   = ((lane >> 3) & 1) * 8;

    #pragma unroll 3
    for (int kt = 0; kt < NKT2; kt++) {
        int s = kt % 3;
        if (kt < NKT2 - 1) asm volatile("cp.async.wait_group 1;" ::: "memory");
        else               asm volatile("cp.async.wait_group 0;" ::: "memory");
        __syncthreads();

        const __half* As = (const __half*)(smb + s * STAGE_BYTES);
        const __half* Bs = As + 128 * STR;

        #pragma unroll
        for (int ks = 0; ks < 4; ks++) {
            int k0 = ks * 16;
            uint32_t a[4][4], b[2][4];
            #pragma unroll
            for (int mt = 0; mt < 4; mt++)
                ldmx4(a[mt], smem_u32(As + (wm + mt * 16 + a_row) * STR + k0 + a_k));
            #pragma unroll
            for (int ntp = 0; ntp < 2; ntp++)
                ldmx4(b[ntp], smem_u32(Bs + (wn + ntp * 16 + b_row) * STR + k0 + b_k));
            #pragma unroll
            for (int mt = 0; mt < 4; mt++) {
                mma_f16(acc[mt][0], a[mt], &b[0][0]);
                mma_f16(acc[mt][1], a[mt], &b[0][2]);
                mma_f16(acc[mt][2], a[mt], &b[1][0]);
                mma_f16(acc[mt][3], a[mt], &b[1][2]);
            }
        }
        if (kt + 2 < NKT2) load_stage((kt + 2) % 3, kt + 2);
    }

    const float sc = (bn < qcols) ? qscale : 1.0f;
    #pragma unroll
    for (int mt = 0; mt < 4; mt++) {
        int row = bm + wm + mt * 16 + lr;
        #pragma unroll
        for (int nt = 0; nt < 4; nt++) {
            int col = bn + wn + nt * 8 + 2 * lc;
            float c0 = acc[mt][nt][0] * sc, c1 = acc[mt][nt][1] * sc;
            float c2 = acc[mt][nt][2] * sc, c3 = acc[mt][nt][3] * sc;
            if (HOUT) {
                __half* C = (__half*)Cv;
                *(__half2*)(C + (size_t)row * N + col) = __floats2half2_rn(c0, c1);
                *(__half2*)(C + (size_t)(row + 8) * N + col) = __floats2half2_rn(c2, c3);
            } else {
                float* C = (float*)Cv;
                *(float2*)(C + (size_t)row * N + col) = make_float2(c0, c1);
                *(float2*)(C + (size_t)(row + 8) * N + col) = make_float2(c2, c3);
            }
        }
    }
}

// ---------------- fp16 mma flash attention (online softmax) -----------------
// 256 thr / 8 warps; 128 q x 64 k per iter; 4-stage K/V; 2 CTA/SM. (round-11)
#define NTK (SEQ/64)
#define NSTG 4
#define AQ_HALVES (128*STR)
#define AK_HALVES (64*STR)
#define ATTN_SMEM ((AQ_HALVES + NSTG*2*AK_HALVES)*2 + NSTG*64*(int)sizeof(float))

__global__ __launch_bounds__(256, 2) void attn_mma_kernel(
        const __half* __restrict__ QKV, const float* __restrict__ MF,
        __half* __restrict__ O)
{
    extern __shared__ char smb[];
    __half* Qs  = (__half*)smb;
    __half* Kss = Qs + AQ_HALVES;
    __half* Vss = Kss + NSTG * AK_HALVES;
    float*  Mks = (float*)(Vss + NSTG * AK_HALVES);

    const int tid  = threadIdx.x;
    const int wid  = tid >> 5;
    const int lane = tid & 31;
    const int lr = lane >> 2;
    const int lc = lane & 3;
    const int wq = wid * 16;
    const int qt = blockIdx.x;
    const int h  = blockIdx.y;
    const int b  = blockIdx.z;

    const int a_row = (lane & 7) + ((lane >> 3) & 1) * 8;
    const int a_k   = (lane >> 4) * 8;
    const int b_row = (lane & 7) + (lane >> 4) * 8;
    const int b_k   = ((lane >> 3) & 1) * 8;

    const size_t qrow0 = (size_t)b * SEQ + (size_t)qt * 128;
    const __half* Qg = QKV + qrow0 * QKVD + h * DKH;
    const __half* Kb = QKV + (size_t)b * SEQ * QKVD + DMODEL + h * DKH;
    const __half* Vb = QKV + (size_t)b * SEQ * QKVD + 2 * DMODEL + h * DKH;
    const float* Mb = MF + (size_t)b * SEQ;

    // Q tile (pre-scaled by 0.125*log2e in GEMM epilogue), in cp.async group 0
    {
        uint32_t qbase = smem_u32(Qs);
        #pragma unroll
        for (int t = 0; t < 4; t++) {
            int idx = tid + t * 256;
            int r = idx >> 3;
            int c = idx & 7;
            cp16(qbase + (uint32_t)(r * STR * 2 + c * 16),
                 Qg + (size_t)r * QKVD + c * 8);
        }
    }

    auto load_stage = [&](int s, int kt) {
        const __half* Kg = Kb + (size_t)kt * 64 * QKVD;
        const __half* Vg = Vb + (size_t)kt * 64 * QKVD;
        uint32_t kbase = smem_u32(Kss + s * AK_HALVES);
        uint32_t vbase = smem_u32(Vss + s * AK_HALVES);
        #pragma unroll
        for (int t = 0; t < 2; t++) {
            int idx = tid + t * 256;
            int r = idx >> 3;
            int c = idx & 7;
            uint32_t off = (uint32_t)(r * STR * 2 + c * 16);
            cp16(kbase + off, Kg + (size_t)r * QKVD + c * 8);
            cp16(vbase + off, Vg + (size_t)r * QKVD + c * 8);
        }
        if (tid < 16)
            cp16(smem_u32(Mks + s * 64) + tid * 16, Mb + kt * 64 + tid * 4);
        CP_COMMIT();
    };

    load_stage(0, 0);   // group 0 also carries the Q cp.asyncs
    load_stage(1, 1);
    load_stage(2, 2);

    // wait for Q (group 0) and hoist Q fragments into registers
    asm volatile("cp.async.wait_group 2;" ::: "memory");
    __syncthreads();
    uint32_t qf[4][4];
    #pragma unroll
    for (int ks = 0; ks < 4; ks++)
        ldmx4(qf[ks], smem_u32(Qs + (wq + a_row) * STR + ks * 16 + a_k));

    float o[8][4];
    #pragma unroll
    for (int nt = 0; nt < 8; nt++)
        #pragma unroll
        for (int i = 0; i < 4; i++) o[nt][i] = 0.0f;
    float mst0 = -1e30f, mst1 = -1e30f, lst0 = 0.0f, lst1 = 0.0f;

    const uint32_t ones2 = packh2(1.0f, 1.0f);
    const uint32_t bones[2] = { ones2, ones2 };

    #pragma unroll 4
    for (int kt = 0; kt < NTK; kt++) {
        int s = kt & 3;
        if (kt < NTK - 2)       asm volatile("cp.async.wait_group 2;" ::: "memory");
        else if (kt == NTK - 2) asm volatile("cp.async.wait_group 1;" ::: "memory");
        else                    asm volatile("cp.async.wait_group 0;" ::: "memory");
        __syncthreads();

        const __half* Kt = Kss + s * AK_HALVES;
        const __half* Vt = Vss + s * AK_HALVES;
        const float* mk = Mks + s * 64;

        // ---- scores: S = (Q*log2e/8) K^T ----
        float sa[8][4];
        #pragma unroll
        for (int nt = 0; nt < 8; nt++)
            #pragma unroll
            for (int i = 0; i < 4; i++) sa[nt][i] = 0.0f;

        #pragma unroll
        for (int ks = 0; ks < 4; ks++) {
            int k0 = ks * 16;
            #pragma unroll
            for (int ntp = 0; ntp < 4; ntp++) {
                uint32_t bb[4];
                ldmx4(bb, smem_u32(Kt + (ntp * 16 + b_row) * STR + k0 + b_k));
                mma_f16(sa[2 * ntp],     qf[ks], &bb[0]);
                mma_f16(sa[2 * ntp + 1], qf[ks], &bb[2]);
            }
        }

        // ---- online softmax (log2 domain) ----
        float rm0 = -1e30f, rm1 = -1e30f;
        #pragma unroll
        for (int nt = 0; nt < 8; nt++) {
            float2 m = *(const float2*)(mk + nt * 8 + 2 * lc);
            sa[nt][0] += m.x; sa[nt][1] += m.y;
            sa[nt][2] += m.x; sa[nt][3] += m.y;
            rm0 = fmaxf(rm0, fmaxf(sa[nt][0], sa[nt][1]));
            rm1 = fmaxf(rm1, fmaxf(sa[nt][2], sa[nt][3]));
        }
        rm0 = fmaxf(rm0, __shfl_xor_sync(0xffffffffu, rm0, 1));
        rm0 = fmaxf(rm0, __shfl_xor_sync(0xffffffffu, rm0, 2));
        rm1 = fmaxf(rm1, __shfl_xor_sync(0xffffffffu, rm1, 1));
        rm1 = fmaxf(rm1, __shfl_xor_sync(0xffffffffu, rm1, 2));

        float nm0 = fmaxf(mst0, rm0), nm1 = fmaxf(mst1, rm1);
        float al0 = exp2f(mst0 - nm0), al1 = exp2f(mst1 - nm1);
        mst0 = nm0; mst1 = nm1;

        // P = 2^(s-m) pairwise in fp16 (ex2.approx.f16x2)
        uint32_t ph[8][2];
        #pragma unroll
        for (int nt = 0; nt < 8; nt++) {
            ph[nt][0] = h2exp2(packh2(sa[nt][0] - nm0, sa[nt][1] - nm0));
            ph[nt][1] = h2exp2(packh2(sa[nt][2] - nm1, sa[nt][3] - nm1));
            o[nt][0] *= al0; o[nt][1] *= al0;
            o[nt][2] *= al1; o[nt][3] *= al1;
        }

        // ---- O += P V ; row-sum(P) via ones-B MMA ----
        float lacc[4] = {0.0f, 0.0f, 0.0f, 0.0f};
        #pragma unroll
        for (int ks = 0; ks < 4; ks++) {
            int k0 = ks * 16;
            uint32_t a[4] = { ph[2 * ks][0], ph[2 * ks][1],
                              ph[2 * ks + 1][0], ph[2 * ks + 1][1] };
            #pragma unroll
            for (int ntp = 0; ntp < 4; ntp++) {
                uint32_t bb[4];
                ldmx4t(bb, smem_u32(Vt + (k0 + a_row) * STR + ntp * 16 + a_k));
                mma_f16(o[2 * ntp],     a, &bb[0]);
                mma_f16(o[2 * ntp + 1], a, &bb[2]);
            }
            mma_f16(lacc, a, bones);
        }
        lst0 = lst0 * al0 + lacc[0];
        lst1 = lst1 * al1 + lacc[2];

        if (kt + 3 < NTK) load_stage((kt + 3) & 3, kt + 3);
    }

    float inv0 = 1.0f / lst0;
    float inv1 = 1.0f / lst1;
    __half* Og = O + qrow0 * DMODEL + h * DKH;
    #pragma unroll
    for (int nt = 0; nt < 8; nt++) {
        int col = nt * 8 + 2 * lc;
        *(__half2*)(Og + (size_t)(wq + lr) * DMODEL + col) =
            __floats2half2_rn(o[nt][0] * inv0, o[nt][1] * inv0);
        *(__half2*)(Og + (size_t)(wq + lr + 8) * DMODEL + col) =
            __floats2half2_rn(o[nt][2] * inv1, o[nt][3] * inv1);
    }
}

// ---------------- launch ---------------------------------------------------
extern "C" void kernel_launch(void* const* d_in, const int* in_sizes, int n_in,
                              void* d_out, int out_size) {
    const float* X    = (const float*)d_in[0];
    const int*   mask = (const int*)d_in[1];
    const float* Wq   = (const float*)d_in[2];
    const float* Wk   = (const float*)d_in[3];
    const float* Wv   = (const float*)d_in[4];
    const float* Wo   = (const float*)d_in[5];
    float* out = (float*)d_out;

    __half *xh, *qkvh, *aoh, *wth;
    float *mf;
    cudaGetSymbolAddress((void**)&xh,   g_XH);
    cudaGetSymbolAddress((void**)&qkvh, g_QKVH);
    cudaGetSymbolAddress((void**)&aoh,  g_AOH);
    cudaGetSymbolAddress((void**)&wth,  g_WTH);
    cudaGetSymbolAddress((void**)&mf,   g_MF);

    cudaFuncSetAttribute(attn_mma_kernel,
                         cudaFuncAttributeMaxDynamicSharedMemorySize, ATTN_SMEM);
    cudaFuncSetAttribute(tgemm_h_kernel<0>,
                         cudaFuncAttributeMaxDynamicSharedMemorySize, TGEMM_SMEM);
    cudaFuncSetAttribute(tgemm_h_kernel<1>,
                         cudaFuncAttributeMaxDynamicSharedMemorySize, TGEMM_SMEM);

    prep_kernel<<<dim3(32, 32, 5), 256>>>(X, mask, Wq, Wk, Wv, Wo, xh, wth, mf);

    // fused Q|K|V projection; Q cols pre-scaled by 0.125*log2e
    tgemm_h_kernel<1><<<dim3(QKVD / 128, MTOT / 128), 256, TGEMM_SMEM>>>(
        xh, wth, qkvh, QKVD, DMODEL, 0.125f * LOG2E);

    attn_mma_kernel<<<dim3(SEQ / 128, NHEAD, BATCH), 256, ATTN_SMEM>>>(qkvh, mf, aoh);

    tgemm_h_kernel<0><<<dim3(DMODEL / 128, MTOT / 128), 256, TGEMM_SMEM>>>(
        aoh, wth + 3 * DMODEL * DMODEL, out, DMODEL, 0, 1.0f);
}